// round 1
// baseline (speedup 1.0000x reference)
#include <cuda_runtime.h>
#include <cuda_bf16.h>

// Shapes (fixed by the problem)
#define BSZ    2
#define NN     384
#define DATOM  512
#define DPAIR  128
#define DHID   32
#define NROWS  (BSZ*NN)          // 768

// Scratch (no cudaMalloc allowed)
__device__ float g_ab[NROWS * 64];            // masked [a|b] per row
__device__ float g_t [NROWS * DPAIR * DHID];  // t[row][p][y], 12.6 MB

// ---------------- f32x2 packed-FMA helpers (sm_103a) ----------------
__device__ __forceinline__ unsigned long long pack2(float x, float y) {
    unsigned long long r;
    asm("mov.b64 %0,{%1,%2};" : "=l"(r) : "f"(x), "f"(y));
    return r;
}
__device__ __forceinline__ void unpack2(unsigned long long v, float& x, float& y) {
    asm("mov.b64 {%0,%1},%2;" : "=f"(x), "=f"(y) : "l"(v));
}
__device__ __forceinline__ void fma2(unsigned long long& d,
                                     unsigned long long a,
                                     unsigned long long b) {
    asm("fma.rn.f32x2 %0,%1,%2,%0;" : "+l"(d) : "l"(a), "l"(b));
}

// ---------------- Stage 1: ab = mask * (m @ W_in^T + b_in) ----------------
// grid 96, block 256. Each block: 8 rows x 64 h outputs.
__global__ __launch_bounds__(256) void stage1_ab(
    const float* __restrict__ m, const float* __restrict__ op_mask,
    const float* __restrict__ W_in, const float* __restrict__ b_in)
{
    __shared__ __align__(16) float m_s[8 * 512];
    __shared__ float w_s[64 * 65];   // pad 65: scalar loads conflict-free
    int tid = threadIdx.x;
    int rbase = blockIdx.x * 8;

    // load 8 m-rows (4096 floats)
    const float4* msrc = (const float4*)(m + (size_t)rbase * 512);
    float4* mdst = (float4*)m_s;
#pragma unroll
    for (int k = 0; k < 4; k++) mdst[tid + k * 256] = msrc[tid + k * 256];

    int h = tid & 63;
    int g = tid >> 6;                // rows g and g+4
    float acc0 = 0.f, acc1 = 0.f;

    for (int kc = 0; kc < 512; kc += 64) {
        __syncthreads();
        // load W_in chunk [64h x 64x] (scalar stores, padded)
#pragma unroll
        for (int k = 0; k < 16; k++) {
            int e = tid + k * 256;
            int hh = e >> 6, x = e & 63;
            w_s[hh * 65 + x] = W_in[(size_t)hh * 512 + kc + x];
        }
        __syncthreads();
#pragma unroll
        for (int xc = 0; xc < 64; xc += 4) {
            float4 a0 = *(const float4*)&m_s[g * 512 + kc + xc];
            float4 a1 = *(const float4*)&m_s[(g + 4) * 512 + kc + xc];
            float w0 = w_s[h * 65 + xc + 0];
            float w1 = w_s[h * 65 + xc + 1];
            float w2 = w_s[h * 65 + xc + 2];
            float w3 = w_s[h * 65 + xc + 3];
            acc0 = fmaf(a0.x, w0, acc0); acc0 = fmaf(a0.y, w1, acc0);
            acc0 = fmaf(a0.z, w2, acc0); acc0 = fmaf(a0.w, w3, acc0);
            acc1 = fmaf(a1.x, w0, acc1); acc1 = fmaf(a1.y, w1, acc1);
            acc1 = fmaf(a1.z, w2, acc1); acc1 = fmaf(a1.w, w3, acc1);
        }
    }
    float bi = b_in[h];
    int r0 = rbase + g, r1 = rbase + g + 4;
    g_ab[(size_t)r0 * 64 + h] = (acc0 + bi) * op_mask[r0];
    g_ab[(size_t)r1 * 64 + h] = (acc1 + bi) * op_mask[r1];
}

// ---------------- Stage 2: t[row,p,y] = sum_x a[row,x] * Wo[p,x,y] ----------------
// grid (16 p-tiles, 24 row-tiles), block 256. Block: 8 p x 32 rows x 32 y.
__global__ __launch_bounds__(256) void stage2_t(const float* __restrict__ W_out)
{
    __shared__ __align__(16) float w_s[8 * 1024];
    __shared__ __align__(16) float a_s[32 * 32];
    int tid = threadIdx.x;
    int pbase = blockIdx.x * 8;
    int rbase = blockIdx.y * 32;

    const float4* wsrc = (const float4*)(W_out + (size_t)pbase * 1024);
    float4* wdst = (float4*)w_s;
#pragma unroll
    for (int k = 0; k < 8; k++) wdst[tid + k * 256] = wsrc[tid + k * 256];
    {
        int r = tid >> 3, c = tid & 7;   // a = first 32 cols of ab
        *(float4*)&a_s[r * 32 + c * 4] =
            *(const float4*)(g_ab + (size_t)(rbase + r) * 64 + c * 4);
    }
    __syncthreads();

    int y = tid & 31, q = tid >> 5;      // lane=y, warp=p-within-tile
    unsigned long long w2[16];           // Wo[pbase+q, x, y] packed over x-pairs
#pragma unroll
    for (int x2 = 0; x2 < 16; x2++) {
        float w0 = w_s[q * 1024 + (2 * x2 + 0) * 32 + y];
        float w1 = w_s[q * 1024 + (2 * x2 + 1) * 32 + y];
        w2[x2] = pack2(w0, w1);
    }
    float* dst = g_t + (size_t)rbase * 4096 + (size_t)(pbase + q) * 32 + y;
#pragma unroll 4
    for (int r = 0; r < 32; r++) {
        unsigned long long acc = 0ull;
#pragma unroll
        for (int xc = 0; xc < 8; xc++) {
            ulonglong2 a2 = *(const ulonglong2*)&a_s[r * 32 + xc * 4]; // broadcast
            fma2(acc, a2.x, w2[2 * xc + 0]);
            fma2(acc, a2.y, w2[2 * xc + 1]);
        }
        float lo, hi; unpack2(acc, lo, hi);
        dst[(size_t)r * 4096] = lo + hi;
    }
}

// ---------------- Stage 3: z[b,i,j,p] = norm*(sum_y t[b,i,p,y]*bvec[b,j,y] + b_out[p]) ----------------
// grid (12 j-tiles, 384 i, 2 b), block 256.
// Block tile: 32 j x 128 p; thread tile 4j x 4p (j += 8, p += 32 interleave
// so every smem LDS.128 is conflict-free or broadcast with row stride 36).
__global__ __launch_bounds__(256, 2) void stage3_z(
    const float* __restrict__ b_out, const float* __restrict__ op_norm,
    float* __restrict__ out)
{
    __shared__ __align__(16) float t_s[128 * 36];
    __shared__ __align__(16) float b_s[32 * 36];
    __shared__ float bo_s[128];

    int tid = threadIdx.x;
    int jtile = blockIdx.x;       // 0..11
    int i = blockIdx.y;           // 0..383
    int b = blockIdx.z;           // 0..1
    int row = b * NN + i;

    // t row: 4096 contiguous floats -> padded smem
    const float4* tsrc = (const float4*)(g_t + (size_t)row * 4096);
#pragma unroll
    for (int k = 0; k < 4; k++) {
        int idx4 = tid + k * 256;
        int e = idx4 * 4;
        int p = e >> 5, y = e & 31;
        *(float4*)&t_s[p * 36 + y] = tsrc[idx4];
    }
    // bvec tile: 32 j rows x 32 y (cols 32..63 of ab)
    {
        int j = tid >> 3, c = tid & 7;
        float4 v = *(const float4*)(g_ab +
            (size_t)(b * NN + jtile * 32 + j) * 64 + 32 + c * 4);
        *(float4*)&b_s[j * 36 + c * 4] = v;
    }
    if (tid < 128) bo_s[tid] = b_out[tid];
    __syncthreads();

    int jt = tid & 7;             // j = jtile*32 + jt + 8u
    int pt = tid >> 3;            // p = pt + 32v
    unsigned long long acc[4][4];
#pragma unroll
    for (int u = 0; u < 4; u++)
#pragma unroll
        for (int v = 0; v < 4; v++) acc[u][v] = 0ull;

#pragma unroll
    for (int yc = 0; yc < 8; yc++) {
        int y = yc * 4;
        ulonglong2 bb[4], tt[4];
#pragma unroll
        for (int u = 0; u < 4; u++)
            bb[u] = *(const ulonglong2*)&b_s[(jt + 8 * u) * 36 + y];
#pragma unroll
        for (int v = 0; v < 4; v++)
            tt[v] = *(const ulonglong2*)&t_s[(pt + 32 * v) * 36 + y];
#pragma unroll
        for (int u = 0; u < 4; u++)
#pragma unroll
            for (int v = 0; v < 4; v++) {
                fma2(acc[u][v], bb[u].x, tt[v].x);
                fma2(acc[u][v], bb[u].y, tt[v].y);
            }
    }

    float norm = op_norm[b];
    size_t obase = (size_t)row * (NN * DPAIR);
#pragma unroll
    for (int u = 0; u < 4; u++) {
        int j = jtile * 32 + jt + 8 * u;
        size_t roff = obase + (size_t)j * DPAIR;
#pragma unroll
        for (int v = 0; v < 4; v++) {
            int p = pt + 32 * v;
            float lo, hi; unpack2(acc[u][v], lo, hi);
            out[roff + p] = (lo + hi + bo_s[p]) * norm;
        }
    }
}

// ---------------- launch ----------------
extern "C" void kernel_launch(void* const* d_in, const int* in_sizes, int n_in,
                              void* d_out, int out_size)
{
    const float* m       = (const float*)d_in[0];
    const float* op_mask = (const float*)d_in[1];
    const float* op_norm = (const float*)d_in[2];
    const float* W_in    = (const float*)d_in[3];
    const float* b_in    = (const float*)d_in[4];
    const float* W_out   = (const float*)d_in[5];
    const float* b_out   = (const float*)d_in[6];
    float* out = (float*)d_out;

    stage1_ab<<<96, 256>>>(m, op_mask, W_in, b_in);
    stage2_t<<<dim3(16, 24), 256>>>(W_out);
    stage3_z<<<dim3(12, NN, BSZ), 256>>>(b_out, op_norm, out);
}

// round 3
// speedup vs baseline: 1.8989x; 1.8989x over previous
#include <cuda_runtime.h>
#include <cuda_bf16.h>
#include <cstdint>

// Shapes (fixed by the problem)
#define BSZ    2
#define NN     384
#define DATOM  512
#define DPAIR  128
#define DHID   32
#define NROWS  (BSZ*NN)          // 768

// Scratch (no cudaMalloc allowed)
__device__ float g_ab[NROWS * 64];            // masked [a|b] per row
__device__ float g_t [NROWS * DPAIR * DHID];  // t[row][p][y], 12.6 MB

// ---------------- f32x2 packed-FMA helpers (sm_103a) ----------------
__device__ __forceinline__ unsigned long long pack2(float x, float y) {
    unsigned long long r;
    asm("mov.b64 %0,{%1,%2};" : "=l"(r) : "f"(x), "f"(y));
    return r;
}
__device__ __forceinline__ void unpack2(unsigned long long v, float& x, float& y) {
    asm("mov.b64 {%0,%1},%2;" : "=f"(x), "=f"(y) : "l"(v));
}
__device__ __forceinline__ void fma2(unsigned long long& d,
                                     unsigned long long a,
                                     unsigned long long b) {
    asm("fma.rn.f32x2 %0,%1,%2,%0;" : "+l"(d) : "l"(a), "l"(b));
}

// ---------------- tf32 helpers ----------------
__device__ __forceinline__ uint32_t f2tf32(float f) {
    uint32_t u;
    asm("cvt.rna.tf32.f32 %0, %1;" : "=r"(u) : "f"(f));
    return u;
}
__device__ __forceinline__ void mma_tf32(float c[4], const uint32_t a[4],
                                         const uint32_t b[2]) {
    asm("mma.sync.aligned.m16n8k8.row.col.f32.tf32.tf32.f32 "
        "{%0,%1,%2,%3}, {%4,%5,%6,%7}, {%8,%9}, {%0,%1,%2,%3};"
        : "+f"(c[0]), "+f"(c[1]), "+f"(c[2]), "+f"(c[3])
        : "r"(a[0]), "r"(a[1]), "r"(a[2]), "r"(a[3]), "r"(b[0]), "r"(b[1]));
}

// ---------------- Stage 1: ab = mask * (m @ W_in^T + b_in) ----------------
// grid 384, block 256. Block: 2 rows x 64 h, 4-way split over x with smem reduce.
__global__ __launch_bounds__(256) void stage1_ab(
    const float* __restrict__ m, const float* __restrict__ op_mask,
    const float* __restrict__ W_in, const float* __restrict__ b_in)
{
    __shared__ __align__(16) float m_s[2 * 512];
    __shared__ float psum[2 * 256];
    int tid = threadIdx.x;
    int rbase = blockIdx.x * 2;

    ((float4*)m_s)[tid] = ((const float4*)(m + (size_t)rbase * 512))[tid];
    __syncthreads();

    int h = tid & 63, xg = tid >> 6;
    const float4* w = (const float4*)(W_in + (size_t)h * 512 + xg * 128);
    float acc0 = 0.f, acc1 = 0.f;
#pragma unroll
    for (int k = 0; k < 32; k++) {
        float4 wv = w[k];
        float4 m0 = *(const float4*)&m_s[xg * 128 + k * 4];
        float4 m1 = *(const float4*)&m_s[512 + xg * 128 + k * 4];
        acc0 = fmaf(wv.x, m0.x, acc0); acc0 = fmaf(wv.y, m0.y, acc0);
        acc0 = fmaf(wv.z, m0.z, acc0); acc0 = fmaf(wv.w, m0.w, acc0);
        acc1 = fmaf(wv.x, m1.x, acc1); acc1 = fmaf(wv.y, m1.y, acc1);
        acc1 = fmaf(wv.z, m1.z, acc1); acc1 = fmaf(wv.w, m1.w, acc1);
    }
    psum[h * 4 + xg] = acc0;
    psum[256 + h * 4 + xg] = acc1;
    __syncthreads();
    if (tid < 128) {
        int r = tid >> 6, hh = tid & 63;
        const float* ps = &psum[r * 256 + hh * 4];
        float s = ps[0] + ps[1] + ps[2] + ps[3];
        g_ab[(size_t)(rbase + r) * 64 + hh] = (s + b_in[hh]) * op_mask[rbase + r];
    }
}

// ---------------- Stage 2: t[row,p,y] = sum_x a[row,x] * Wo[p,x,y] ----------------
// grid (16 p-tiles, 24 row-tiles), block 256. Block: 8 p x 32 rows x 32 y.
__global__ __launch_bounds__(256) void stage2_t(const float* __restrict__ W_out)
{
    __shared__ __align__(16) float w_s[8 * 1024];
    __shared__ __align__(16) float a_s[32 * 32];
    int tid = threadIdx.x;
    int pbase = blockIdx.x * 8;
    int rbase = blockIdx.y * 32;

    const float4* wsrc = (const float4*)(W_out + (size_t)pbase * 1024);
    float4* wdst = (float4*)w_s;
#pragma unroll
    for (int k = 0; k < 8; k++) wdst[tid + k * 256] = wsrc[tid + k * 256];
    {
        int r = tid >> 3, c = tid & 7;   // a = first 32 cols of ab
        *(float4*)&a_s[r * 32 + c * 4] =
            *(const float4*)(g_ab + (size_t)(rbase + r) * 64 + c * 4);
    }
    __syncthreads();

    int y = tid & 31, q = tid >> 5;      // lane=y, warp=p-within-tile
    unsigned long long w2[16];           // Wo[pbase+q, x, y] packed over x-pairs
#pragma unroll
    for (int x2 = 0; x2 < 16; x2++) {
        float w0 = w_s[q * 1024 + (2 * x2 + 0) * 32 + y];
        float w1 = w_s[q * 1024 + (2 * x2 + 1) * 32 + y];
        w2[x2] = pack2(w0, w1);
    }
    float* dst = g_t + (size_t)rbase * 4096 + (size_t)(pbase + q) * 32 + y;
#pragma unroll 4
    for (int r = 0; r < 32; r++) {
        unsigned long long acc = 0ull;
#pragma unroll
        for (int xc = 0; xc < 8; xc++) {
            ulonglong2 a2 = *(const ulonglong2*)&a_s[r * 32 + xc * 4]; // broadcast
            fma2(acc, a2.x, w2[2 * xc + 0]);
            fma2(acc, a2.y, w2[2 * xc + 1]);
        }
        float lo, hi; unpack2(acc, lo, hi);
        dst[(size_t)r * 4096] = lo + hi;
    }
}

// ---------------- Stage 3 (warp MMA, tf32): per (b,i): Z[j,p] = bv[j,:] . t[p,:] ----------------
// A = bv (M = j, 128), B = t (N = p, 128), K = 32. grid (3 jtiles, 384 i, 2 b), block 256.
// Warp grid 4(M) x 2(N): warp tile 32j x 64p. m16n8k8: 2 m-tiles x 8 n-tiles x 4 k-steps.
#define S3PAD 36
__global__ __launch_bounds__(256) void stage3_mma(
    const float* __restrict__ b_out, const float* __restrict__ op_norm,
    float* __restrict__ out)
{
    __shared__ __align__(16) uint32_t a_s[128 * S3PAD];  // bv tile [j][y] (tf32)
    __shared__ __align__(16) uint32_t t_s[128 * S3PAD];  // t  tile [p][y] (tf32)
    __shared__ float bo_s[128];

    int tid = threadIdx.x;
    int jbase = blockIdx.x * 128;
    int i = blockIdx.y;
    int b = blockIdx.z;
    int row = b * NN + i;

    // fill t tile: g_t row = 4096 contiguous floats, [p][y]
    const float4* tsrc = (const float4*)(g_t + (size_t)row * 4096);
#pragma unroll
    for (int k = 0; k < 4; k++) {
        int idx4 = tid + k * 256;
        int e = idx4 * 4, p = e >> 5, y = e & 31;
        float4 v = tsrc[idx4];
        uint32_t* d = &t_s[p * S3PAD + y];
        d[0] = f2tf32(v.x); d[1] = f2tf32(v.y); d[2] = f2tf32(v.z); d[3] = f2tf32(v.w);
    }
    // fill bv tile: rows j, cols 32..63 of g_ab
#pragma unroll
    for (int k = 0; k < 4; k++) {
        int idx4 = tid + k * 256;
        int e = idx4 * 4, j = e >> 5, c = e & 31;
        float4 v = *(const float4*)(g_ab + (size_t)(b * NN + jbase + j) * 64 + 32 + c);
        uint32_t* d = &a_s[j * S3PAD + c];
        d[0] = f2tf32(v.x); d[1] = f2tf32(v.y); d[2] = f2tf32(v.z); d[3] = f2tf32(v.w);
    }
    if (tid < 128) bo_s[tid] = b_out[tid];
    __syncthreads();

    int wid = tid >> 5, lane = tid & 31;
    int g = lane >> 2, tg = lane & 3;
    int wm = wid & 3;          // j block of 32
    int wn = wid >> 2;         // p block of 64

    float c[2][8][4];
#pragma unroll
    for (int mt = 0; mt < 2; mt++)
#pragma unroll
        for (int nt = 0; nt < 8; nt++)
#pragma unroll
            for (int r = 0; r < 4; r++) c[mt][nt][r] = 0.f;

#pragma unroll
    for (int ks = 0; ks < 4; ks++) {
        int kk = ks * 8;
        uint32_t af[2][4];
#pragma unroll
        for (int mt = 0; mt < 2; mt++) {
            int r0 = wm * 32 + mt * 16;
            af[mt][0] = a_s[(r0 + g) * S3PAD + kk + tg];
            af[mt][1] = a_s[(r0 + 8 + g) * S3PAD + kk + tg];
            af[mt][2] = a_s[(r0 + g) * S3PAD + kk + tg + 4];
            af[mt][3] = a_s[(r0 + 8 + g) * S3PAD + kk + tg + 4];
        }
        uint32_t bf[8][2];
#pragma unroll
        for (int nt = 0; nt < 8; nt++) {
            int cc = wn * 64 + nt * 8 + g;
            bf[nt][0] = t_s[cc * S3PAD + kk + tg];
            bf[nt][1] = t_s[cc * S3PAD + kk + tg + 4];
        }
#pragma unroll
        for (int mt = 0; mt < 2; mt++)
#pragma unroll
            for (int nt = 0; nt < 8; nt++)
                mma_tf32(c[mt][nt], af[mt], bf[nt]);
    }

    // epilogue: z = acc*norm + b_out[p]*norm; thread owns (j, p..p+1) pairs
    float norm = op_norm[b];
    size_t obase = ((size_t)row * NN + jbase) * DPAIR;
#pragma unroll
    for (int mt = 0; mt < 2; mt++) {
        int j0 = wm * 32 + mt * 16 + g;
#pragma unroll
        for (int nt = 0; nt < 8; nt++) {
            int p = wn * 64 + nt * 8 + 2 * tg;
            float bz0 = bo_s[p] * norm, bz1 = bo_s[p + 1] * norm;
            float2 v0 = make_float2(fmaf(c[mt][nt][0], norm, bz0),
                                    fmaf(c[mt][nt][1], norm, bz1));
            float2 v1 = make_float2(fmaf(c[mt][nt][2], norm, bz0),
                                    fmaf(c[mt][nt][3], norm, bz1));
            *(float2*)(out + obase + (size_t)j0 * DPAIR + p) = v0;
            *(float2*)(out + obase + (size_t)(j0 + 8) * DPAIR + p) = v1;
        }
    }
}

// ---------------- launch ----------------
extern "C" void kernel_launch(void* const* d_in, const int* in_sizes, int n_in,
                              void* d_out, int out_size)
{
    const float* m       = (const float*)d_in[0];
    const float* op_mask = (const float*)d_in[1];
    const float* op_norm = (const float*)d_in[2];
    const float* W_in    = (const float*)d_in[3];
    const float* b_in    = (const float*)d_in[4];
    const float* W_out   = (const float*)d_in[5];
    const float* b_out   = (const float*)d_in[6];
    float* out = (float*)d_out;

    stage1_ab<<<384, 256>>>(m, op_mask, W_in, b_in);
    stage2_t<<<dim3(16, 24), 256>>>(W_out);
    stage3_mma<<<dim3(3, NN, BSZ), 256>>>(b_out, op_norm, out);
}